// round 2
// baseline (speedup 1.0000x reference)
#include <cuda_runtime.h>

#define L_ 1024
#define B_ 8
#define E_ 512
#define H_ 8
#define D_ 64
#define ROWS_ (L_*B_)          /* 8192 */
#define QKV_LD (3*E_)          /* 1536 */

// ---------------- scratch (no cudaMalloc allowed) ----------------
__device__ float g_qkv[(size_t)ROWS_ * QKV_LD];       // 50.3 MB
__device__ float g_att[(size_t)ROWS_ * E_];           // 16.8 MB
__device__ unsigned char g_edge8[(size_t)B_ * L_ * L_]; // 8.4 MB
__device__ int g_is64;

// ---------------- kernel -1: detect edge dtype (int32 vs int64) ----------------
// Edge values are < 16. If buffer is int64 (LE), every odd 32-bit word is 0.
// If int32, odd words are random edge values (all-zero prob ~16^-512).
__global__ void detect_edge_dtype_kernel(const unsigned int* __restrict__ e)
{
    if (threadIdx.x == 0 && blockIdx.x == 0) {
        int is64 = 1;
        for (int i = 0; i < 512; i++) {
            if (e[2 * i + 1] != 0u) { is64 = 0; break; }
        }
        g_is64 = is64;
    }
}

// ---------------- kernel 0: pack edge (int32 or int64) -> uint8 ----------------
__global__ __launch_bounds__(256) void pack_edge_kernel(const void* __restrict__ edge)
{
    const int i = blockIdx.x * blockDim.x + threadIdx.x;   // each handles 4 elems
    uchar4 u;
    if (g_is64) {
        const long long* e = (const long long*)edge;
        u.x = (unsigned char)e[(size_t)i*4 + 0];
        u.y = (unsigned char)e[(size_t)i*4 + 1];
        u.z = (unsigned char)e[(size_t)i*4 + 2];
        u.w = (unsigned char)e[(size_t)i*4 + 3];
    } else {
        const int4 v = *(const int4*)((const int*)edge + (size_t)i*4);
        u.x = (unsigned char)v.x; u.y = (unsigned char)v.y;
        u.z = (unsigned char)v.z; u.w = (unsigned char)v.w;
    }
    *(uchar4*)(g_edge8 + (size_t)i*4) = u;
}

// ---------------- generic SGEMM: C[M,N] = A[M,K] * B[N,K]^T + bias ----------------
// BM=BN=128, BK=16, 256 threads, 8x8 microtile (interleaved by 16)
__global__ __launch_bounds__(256) void gemm_abt_kernel(
    const float* __restrict__ A, const float* __restrict__ Bm,
    const float* __restrict__ bias, float* __restrict__ C,
    int N, int K)
{
    __shared__ float As[16][128];
    __shared__ float Bs[16][128];
    const int t  = threadIdx.x;
    const int tx = t & 15, ty = t >> 4;
    const int bm = blockIdx.y << 7;
    const int bn = blockIdx.x << 7;
    const int lr = t >> 2;            // 0..63
    const int lc = (t & 3) << 2;      // 0,4,8,12

    const float* Ap = A  + (size_t)(bm + lr) * K + lc;
    const float* Bp = Bm + (size_t)(bn + lr) * K + lc;

    float acc[8][8];
#pragma unroll
    for (int r = 0; r < 8; r++)
#pragma unroll
        for (int c = 0; c < 8; c++) acc[r][c] = 0.f;

    for (int k0 = 0; k0 < K; k0 += 16) {
        const float4 a0 = *(const float4*)(Ap + k0);
        const float4 a1 = *(const float4*)(Ap + (size_t)64 * K + k0);
        const float4 b0 = *(const float4*)(Bp + k0);
        const float4 b1 = *(const float4*)(Bp + (size_t)64 * K + k0);
        __syncthreads();
        As[lc+0][lr]    = a0.x; As[lc+1][lr]    = a0.y; As[lc+2][lr]    = a0.z; As[lc+3][lr]    = a0.w;
        As[lc+0][lr+64] = a1.x; As[lc+1][lr+64] = a1.y; As[lc+2][lr+64] = a1.z; As[lc+3][lr+64] = a1.w;
        Bs[lc+0][lr]    = b0.x; Bs[lc+1][lr]    = b0.y; Bs[lc+2][lr]    = b0.z; Bs[lc+3][lr]    = b0.w;
        Bs[lc+0][lr+64] = b1.x; Bs[lc+1][lr+64] = b1.y; Bs[lc+2][lr+64] = b1.z; Bs[lc+3][lr+64] = b1.w;
        __syncthreads();
#pragma unroll
        for (int kk = 0; kk < 16; kk++) {
            float af[8], bf[8];
#pragma unroll
            for (int r = 0; r < 8; r++) af[r] = As[kk][ty + (r << 4)];
#pragma unroll
            for (int c = 0; c < 8; c++) bf[c] = Bs[kk][tx + (c << 4)];
#pragma unroll
            for (int r = 0; r < 8; r++)
#pragma unroll
                for (int c = 0; c < 8; c++)
                    acc[r][c] = fmaf(af[r], bf[c], acc[r][c]);
        }
    }
#pragma unroll
    for (int r = 0; r < 8; r++) {
        const int row = bm + ty + (r << 4);
#pragma unroll
        for (int c = 0; c < 8; c++) {
            const int col = bn + tx + (c << 4);
            C[(size_t)row * N + col] = acc[r][c] + bias[col];
        }
    }
}

// ---------------- fused flash attention with edge bias ----------------
// grid (L/128, B*H), 256 threads.  BQ=128, BKV=64.
// Thread (tx,ty): S rows i = ty+16r (r<8), cols j = tx+16c (c<4).
#define PITCH 65

__global__ __launch_bounds__(256) void attn_kernel(
    const float* __restrict__ attn_mask,
    const unsigned char* __restrict__ kpm,
    const float* __restrict__ edge_tab)
{
    extern __shared__ float sm[];
    float* Qs = sm;                                      // 128*PITCH
    float* Ks = Qs + 128 * PITCH;                        // 64*PITCH
    float* Vs = Ks + 64 * PITCH;                         // 64*PITCH
    float* Ss = Vs + 64 * PITCH;                         // 128*PITCH
    unsigned char* Es = (unsigned char*)(Ss + 128 * PITCH); // 128*64 bytes (16B aligned)
    float* et    = (float*)(Es + 128 * 64);              // 16
    float* row_m = et + 16;                              // 128
    float* row_l = row_m + 128;                          // 128
    float* row_c = row_l + 128;                          // 128
    float* kps   = row_c + 128;                          // 64

    const int t  = threadIdx.x;
    const int tx = t & 15, ty = t >> 4;
    const int qb = blockIdx.x;
    const int bh = blockIdx.y;
    const int b  = bh >> 3, h = bh & 7;
    const int q0 = qb << 7;

    if (t < 16)  et[t] = edge_tab[t * H_ + h];
    if (t < 128) { row_m[t] = -1e30f; row_l[t] = 0.f; }

    // load Q tile [128, 64]
    {
        const int r  = t >> 1;
        const int c0 = (t & 1) << 5;
        const float* src = g_qkv + (size_t)((q0 + r) * B_ + b) * QKV_LD + h * D_ + c0;
#pragma unroll
        for (int q = 0; q < 8; q++) {
            const float4 v = *(const float4*)(src + q * 4);
            Qs[r*PITCH + c0 + q*4 + 0] = v.x;
            Qs[r*PITCH + c0 + q*4 + 1] = v.y;
            Qs[r*PITCH + c0 + q*4 + 2] = v.z;
            Qs[r*PITCH + c0 + q*4 + 3] = v.w;
        }
    }

    float o[8][4];
#pragma unroll
    for (int r = 0; r < 8; r++)
#pragma unroll
        for (int c = 0; c < 4; c++) o[r][c] = 0.f;

    const size_t edge_base = (size_t)b << 20;   // b * L * L

    for (int kb = 0; kb < 16; kb++) {
        const int m0 = kb << 6;
        __syncthreads();   // previous iteration done reading Ks/Vs/Ss

        // K and V tiles [64, 64]
        {
            const int r  = t >> 2;
            const int c0 = (t & 3) << 4;
            const float* kq = g_qkv + (size_t)((m0 + r) * B_ + b) * QKV_LD + E_ + h * D_ + c0;
#pragma unroll
            for (int q = 0; q < 4; q++) {
                const float4 kv = *(const float4*)(kq + q * 4);
                Ks[r*PITCH + c0 + q*4 + 0] = kv.x;
                Ks[r*PITCH + c0 + q*4 + 1] = kv.y;
                Ks[r*PITCH + c0 + q*4 + 2] = kv.z;
                Ks[r*PITCH + c0 + q*4 + 3] = kv.w;
                const float4 vv = *(const float4*)(kq + E_ + q * 4);
                Vs[r*PITCH + c0 + q*4 + 0] = vv.x;
                Vs[r*PITCH + c0 + q*4 + 1] = vv.y;
                Vs[r*PITCH + c0 + q*4 + 2] = vv.z;
                Vs[r*PITCH + c0 + q*4 + 3] = vv.w;
            }
        }
        // attn_mask tile staged into Ss (Ss is free until S epilogue)
        {
            const int r  = t >> 1;
            const int c0 = (t & 1) << 5;
            const float* mp = attn_mask + (size_t)(q0 + r) * L_ + m0 + c0;
#pragma unroll
            for (int q = 0; q < 8; q++) {
                const float4 v = *(const float4*)(mp + q * 4);
                Ss[r*PITCH + c0 + q*4 + 0] = v.x;
                Ss[r*PITCH + c0 + q*4 + 1] = v.y;
                Ss[r*PITCH + c0 + q*4 + 2] = v.z;
                Ss[r*PITCH + c0 + q*4 + 3] = v.w;
            }
        }
        // edge tile [128, 64] uint8
        {
            int idx = t * 2;
#pragma unroll
            for (int q = 0; q < 2; q++, idx++) {
                const int r   = idx >> 2;
                const int c16 = (idx & 3) << 4;
                const uint4 v = *(const uint4*)(g_edge8 + edge_base + (size_t)(q0 + r) * L_ + m0 + c16);
                *(uint4*)(Es + r * 64 + c16) = v;
            }
        }
        if (t < 64) kps[t] = kpm[b * L_ + m0 + t] ? -1e30f : 0.f;
        __syncthreads();

        // S = Q K^T  (128x64x64)
        float s[8][4];
#pragma unroll
        for (int r = 0; r < 8; r++)
#pragma unroll
            for (int c = 0; c < 4; c++) s[r][c] = 0.f;
#pragma unroll 8
        for (int d = 0; d < D_; d++) {
            float qf[8], kf[4];
#pragma unroll
            for (int r = 0; r < 8; r++) qf[r] = Qs[(ty + (r << 4)) * PITCH + d];
#pragma unroll
            for (int c = 0; c < 4; c++) kf[c] = Ks[(tx + (c << 4)) * PITCH + d];
#pragma unroll
            for (int r = 0; r < 8; r++)
#pragma unroll
                for (int c = 0; c < 4; c++)
                    s[r][c] = fmaf(qf[r], kf[c], s[r][c]);
        }
        // epilogue: scale + mask + edge bias + key padding, write S into Ss
#pragma unroll
        for (int r = 0; r < 8; r++) {
            const int i = ty + (r << 4);
#pragma unroll
            for (int c = 0; c < 4; c++) {
                const int j = tx + (c << 4);
                const float v = s[r][c] * 0.125f + Ss[i * PITCH + j]
                              + et[Es[i * 64 + j]] + kps[j];
                Ss[i * PITCH + j] = v;
            }
        }
        __syncthreads();

        // online softmax: 2 threads per row
        {
            const int row = t >> 1;
            const int c0  = (t & 1) << 5;
            float* Sr = Ss + row * PITCH + c0;
            float mx = -1e30f;
#pragma unroll
            for (int j = 0; j < 32; j++) mx = fmaxf(mx, Sr[j]);
            mx = fmaxf(mx, __shfl_xor_sync(0xffffffffu, mx, 1));
            const float m_old = row_m[row];
            const float m_new = fmaxf(m_old, mx);
            float sum = 0.f;
#pragma unroll
            for (int j = 0; j < 32; j++) {
                const float p = __expf(Sr[j] - m_new);
                Sr[j] = p;
                sum += p;
            }
            sum += __shfl_xor_sync(0xffffffffu, sum, 1);
            if ((t & 1) == 0) {
                row_c[row] = __expf(m_old - m_new);
                row_m[row] = m_new;
                row_l[row] = row_l[row] * row_c[row] + sum;
            }
        }
        __syncthreads();

        // rescale O, then O += P V
#pragma unroll
        for (int r = 0; r < 8; r++) {
            const float cr = row_c[ty + (r << 4)];
#pragma unroll
            for (int c = 0; c < 4; c++) o[r][c] *= cr;
        }
#pragma unroll 8
        for (int m = 0; m < 64; m++) {
            float pf[8], vf[4];
#pragma unroll
            for (int r = 0; r < 8; r++) pf[r] = Ss[(ty + (r << 4)) * PITCH + m];
#pragma unroll
            for (int c = 0; c < 4; c++) vf[c] = Vs[m * PITCH + tx + (c << 4)];
#pragma unroll
            for (int r = 0; r < 8; r++)
#pragma unroll
                for (int c = 0; c < 4; c++)
                    o[r][c] = fmaf(pf[r], vf[c], o[r][c]);
        }
    }

    // normalize and write to g_att as [L,B,H,D]
#pragma unroll
    for (int r = 0; r < 8; r++) {
        const int i = ty + (r << 4);
        const float inv = 1.f / row_l[i];
#pragma unroll
        for (int c = 0; c < 4; c++) {
            const int j = tx + (c << 4);
            g_att[(size_t)((q0 + i) * B_ + b) * E_ + h * D_ + j] = o[r][c] * inv;
        }
    }
}

// ---------------- launch ----------------
extern "C" void kernel_launch(void* const* d_in, const int* in_sizes, int n_in,
                              void* d_out, int out_size)
{
    const float*         x         = (const float*)d_in[0];
    const void*          edge      = d_in[1];
    const float*         attn_mask = (const float*)d_in[2];
    const unsigned char* kpm       = (const unsigned char*)d_in[3];
    const float*         in_w      = (const float*)d_in[4];
    const float*         in_b      = (const float*)d_in[5];
    const float*         out_w     = (const float*)d_in[6];
    const float*         out_b     = (const float*)d_in[7];
    const float*         edge_tab  = (const float*)d_in[8];
    float* out = (float*)d_out;

    float *qkv_ptr = nullptr, *att_ptr = nullptr;
    cudaGetSymbolAddress((void**)&qkv_ptr, g_qkv);
    cudaGetSymbolAddress((void**)&att_ptr, g_att);

    // -1) detect edge dtype (int32 vs int64); values < 16 so int64 odd words are 0
    detect_edge_dtype_kernel<<<1, 32>>>((const unsigned int*)edge);

    // 0) pack edge -> uint8
    pack_edge_kernel<<<(B_ * L_ * L_) / (256 * 4), 256>>>(edge);

    // 1) QKV projection: [8192,1536] = x[8192,512] @ in_w[1536,512]^T + in_b
    gemm_abt_kernel<<<dim3(QKV_LD / 128, ROWS_ / 128), 256>>>(x, in_w, in_b, qkv_ptr, QKV_LD, E_);

    // 2) fused attention
    const size_t shmem = (size_t)(128 * PITCH + 64 * PITCH + 64 * PITCH + 128 * PITCH) * 4
                       + 128 * 64
                       + (size_t)(16 + 3 * 128 + 64) * 4;
    cudaFuncSetAttribute(attn_kernel, cudaFuncAttributeMaxDynamicSharedMemorySize, (int)shmem);
    attn_kernel<<<dim3(L_ / 128, B_ * H_), 256, shmem>>>(attn_mask, kpm, edge_tab);

    // 3) output projection: [8192,512] = g_att @ out_w[512,512]^T + out_b
    gemm_abt_kernel<<<dim3(E_ / 128, ROWS_ / 128), 256>>>(att_ptr, out_w, out_b, out, E_, E_);
}

// round 4
// speedup vs baseline: 1.9571x; 1.9571x over previous
#include <cuda_runtime.h>
#include <cuda_bf16.h>
#include <cstdint>

#define L_ 1024
#define B_ 8
#define E_ 512
#define H_ 8
#define D_ 64
#define ROWS_ (L_*B_)          /* 8192 */
#define QKV_LD (3*E_)          /* 1536 */

// ---------------- scratch (no cudaMalloc allowed) ----------------
__device__ float g_qkv[(size_t)ROWS_ * QKV_LD];         // 50.3 MB
__device__ float g_att[(size_t)ROWS_ * E_];             // 16.8 MB
__device__ unsigned char g_edge8[(size_t)B_ * L_ * L_]; // 8.4 MB
__device__ int g_is64;

// ================= helpers (plain sm_103-safe: mma.sync + ldmatrix) =================
__device__ __forceinline__ uint32_t cvta_smem(const void* p) {
    uint32_t a;
    asm("{ .reg .u64 t; cvta.to.shared.u64 t, %1; cvt.u32.u64 %0, t; }" : "=r"(a) : "l"(p));
    return a;
}
__device__ __forceinline__ void ldsm4(uint32_t& r0, uint32_t& r1, uint32_t& r2, uint32_t& r3, uint32_t a) {
    asm volatile("ldmatrix.sync.aligned.m8n8.x4.shared.b16 {%0,%1,%2,%3}, [%4];"
                 : "=r"(r0), "=r"(r1), "=r"(r2), "=r"(r3) : "r"(a));
}
__device__ __forceinline__ void ldsm2(uint32_t& r0, uint32_t& r1, uint32_t a) {
    asm volatile("ldmatrix.sync.aligned.m8n8.x2.shared.b16 {%0,%1}, [%2];"
                 : "=r"(r0), "=r"(r1) : "r"(a));
}
__device__ __forceinline__ void ldsm2t(uint32_t& r0, uint32_t& r1, uint32_t a) {
    asm volatile("ldmatrix.sync.aligned.m8n8.x2.trans.shared.b16 {%0,%1}, [%2];"
                 : "=r"(r0), "=r"(r1) : "r"(a));
}
__device__ __forceinline__ void mma_bf16(float& d0, float& d1, float& d2, float& d3,
                                         uint32_t a0, uint32_t a1, uint32_t a2, uint32_t a3,
                                         uint32_t b0, uint32_t b1) {
    asm volatile("mma.sync.aligned.m16n8k16.row.col.f32.bf16.bf16.f32 "
                 "{%0,%1,%2,%3}, {%4,%5,%6,%7}, {%8,%9}, {%0,%1,%2,%3};"
                 : "+f"(d0), "+f"(d1), "+f"(d2), "+f"(d3)
                 : "r"(a0), "r"(a1), "r"(a2), "r"(a3), "r"(b0), "r"(b1));
}
__device__ __forceinline__ uint32_t pack2h(__nv_bfloat16 a, __nv_bfloat16 b) {
    return (uint32_t)__bfloat16_as_ushort(a) | ((uint32_t)__bfloat16_as_ushort(b) << 16);
}
__device__ __forceinline__ uint32_t packbf(float x, float y) {
    return pack2h(__float2bfloat16(x), __float2bfloat16(y));
}
// split 4 fp32 -> 4 bf16 hi + 4 bf16 lo
__device__ __forceinline__ void split4(const float4 v, uint2& hi, uint2& lo) {
    __nv_bfloat16 h0 = __float2bfloat16(v.x), h1 = __float2bfloat16(v.y);
    __nv_bfloat16 h2 = __float2bfloat16(v.z), h3 = __float2bfloat16(v.w);
    hi.x = pack2h(h0, h1); hi.y = pack2h(h2, h3);
    lo.x = packbf(v.x - __bfloat162float(h0), v.y - __bfloat162float(h1));
    lo.y = packbf(v.z - __bfloat162float(h2), v.w - __bfloat162float(h3));
}

// ---------------- kernel -1: detect edge dtype (int32 vs int64) ----------------
__global__ void detect_edge_dtype_kernel(const unsigned int* __restrict__ e)
{
    const int t = threadIdx.x;
    unsigned v = 0;
    for (int i = t; i < 512; i += 32) v |= e[2 * i + 1];
    const unsigned any = __ballot_sync(0xffffffffu, v != 0u);
    if (t == 0) g_is64 = (any == 0u) ? 1 : 0;
}

// ---------------- kernel 0: pack edge (int32 or int64) -> uint8 ----------------
__global__ __launch_bounds__(256) void pack_edge_kernel(const void* __restrict__ edge)
{
    const int i = blockIdx.x * blockDim.x + threadIdx.x;
    uchar4 u;
    if (g_is64) {
        const long long* e = (const long long*)edge;
        u.x = (unsigned char)e[(size_t)i*4 + 0];
        u.y = (unsigned char)e[(size_t)i*4 + 1];
        u.z = (unsigned char)e[(size_t)i*4 + 2];
        u.w = (unsigned char)e[(size_t)i*4 + 3];
    } else {
        const int4 v = *(const int4*)((const int*)edge + (size_t)i*4);
        u.x = (unsigned char)v.x; u.y = (unsigned char)v.y;
        u.z = (unsigned char)v.z; u.w = (unsigned char)v.w;
    }
    *(uchar4*)(g_edge8 + (size_t)i*4) = u;
}

// ================= HMMA GEMM: C[M,N] = A[M,K]·B[N,K]^T + bias =================
// fp32 -> bf16 hi/lo split at staging; 3 mma products per tile (hh + hl + lh).
// BM=BN=128, BK=32, 256 threads = 8 warps as 4(m)x2(n), warp tile 32x64.
#define GP 40                         /* bf16 pitch for 32-col tiles */
#define GTILE (128*GP*2)              /* 10240 B per tile */
#define GSTG  (4*GTILE)               /* Ah, Al, Bh, Bl = 40960 B */
#define GEMM_SMEM (2*GSTG)

__global__ __launch_bounds__(256) void gemm_hmma(
    const float* __restrict__ A, const float* __restrict__ Bm,
    const float* __restrict__ bias, float* __restrict__ C,
    int N, int K)
{
    extern __shared__ char smc[];
    const uint32_t sb = cvta_smem(smc);
    const int t = threadIdx.x, wid = t >> 5, lane = t & 31;
    const int wm = wid & 3, wn = wid >> 2;
    const int bm = blockIdx.y << 7, bn = blockIdx.x << 7;

    const int row = t >> 1, kc = (t & 1) << 4;
    const float* Ap = A  + (size_t)(bm + row) * K + kc;
    const float* Bp = Bm + (size_t)(bn + row) * K + kc;

    float4 ra[4], rb[4];
#pragma unroll
    for (int j = 0; j < 4; j++) { ra[j] = *(const float4*)(Ap + j*4); rb[j] = *(const float4*)(Bp + j*4); }

    const uint32_t stoff = (uint32_t)(row * GP + kc) * 2;
    // store current ra/rb into stage buf
    {
        char* s = smc + stoff;
#pragma unroll
        for (int j = 0; j < 4; j++) {
            uint2 hi, lo;
            split4(ra[j], hi, lo);
            *(uint2*)(s + j*8) = hi;
            *(uint2*)(s + GTILE + j*8) = lo;
            split4(rb[j], hi, lo);
            *(uint2*)(s + 2*GTILE + j*8) = hi;
            *(uint2*)(s + 3*GTILE + j*8) = lo;
        }
    }
    __syncthreads();

    float acc[2][8][4];
#pragma unroll
    for (int i = 0; i < 2; i++)
#pragma unroll
        for (int j = 0; j < 8; j++)
#pragma unroll
            for (int c = 0; c < 4; c++) acc[i][j][c] = 0.f;

    // ldmatrix lane addressing (byte offsets within a tile)
    const uint32_t a_row = (uint32_t)((lane & 7) + ((lane >> 3) & 1) * 8);
    const uint32_t a_kb  = (uint32_t)((lane >> 4) << 4);
    const uint32_t b_row = (uint32_t)(lane & 7);
    const uint32_t b_kb  = (uint32_t)(((lane >> 3) & 1) << 4);

    const int niter = K >> 5;
    for (int it = 0; it < niter; it++) {
        if (it + 1 < niter) {
            const float* ap = Ap + (it + 1) * 32;
            const float* bp = Bp + (it + 1) * 32;
#pragma unroll
            for (int j = 0; j < 4; j++) { ra[j] = *(const float4*)(ap + j*4); rb[j] = *(const float4*)(bp + j*4); }
        }
        const uint32_t s = sb + (uint32_t)((it & 1) * GSTG);
#pragma unroll
        for (int kk = 0; kk < 2; kk++) {
            uint32_t ah[2][4], al[2][4];
#pragma unroll
            for (int i = 0; i < 2; i++) {
                const uint32_t r = (uint32_t)(wm * 32 + i * 16) + a_row;
                const uint32_t ad = s + r * (GP*2) + (uint32_t)(kk * 32) + a_kb;
                ldsm4(ah[i][0], ah[i][1], ah[i][2], ah[i][3], ad);
                ldsm4(al[i][0], al[i][1], al[i][2], al[i][3], ad + GTILE);
            }
#pragma unroll
            for (int j = 0; j < 8; j++) {
                const uint32_t r = (uint32_t)(wn * 64 + j * 8) + b_row;
                const uint32_t bd = s + 2*GTILE + r * (GP*2) + (uint32_t)(kk * 32) + b_kb;
                uint32_t bh0, bh1, bl0, bl1;
                ldsm2(bh0, bh1, bd);
                ldsm2(bl0, bl1, bd + GTILE);
#pragma unroll
                for (int i = 0; i < 2; i++) {
                    mma_bf16(acc[i][j][0], acc[i][j][1], acc[i][j][2], acc[i][j][3],
                             ah[i][0], ah[i][1], ah[i][2], ah[i][3], bh0, bh1);
                    mma_bf16(acc[i][j][0], acc[i][j][1], acc[i][j][2], acc[i][j][3],
                             ah[i][0], ah[i][1], ah[i][2], ah[i][3], bl0, bl1);
                    mma_bf16(acc[i][j][0], acc[i][j][1], acc[i][j][2], acc[i][j][3],
                             al[i][0], al[i][1], al[i][2], al[i][3], bh0, bh1);
                }
            }
        }
        __syncthreads();
        if (it + 1 < niter) {
            char* sn = smc + ((it + 1) & 1) * GSTG + stoff;
#pragma unroll
            for (int j = 0; j < 4; j++) {
                uint2 hi, lo;
                split4(ra[j], hi, lo);
                *(uint2*)(sn + j*8) = hi;
                *(uint2*)(sn + GTILE + j*8) = lo;
                split4(rb[j], hi, lo);
                *(uint2*)(sn + 2*GTILE + j*8) = hi;
                *(uint2*)(sn + 3*GTILE + j*8) = lo;
            }
            __syncthreads();
        }
    }

    // epilogue
#pragma unroll
    for (int i = 0; i < 2; i++) {
        const int r0 = bm + wm * 32 + i * 16 + (lane >> 2);
#pragma unroll
        for (int j = 0; j < 8; j++) {
            const int c = bn + wn * 64 + j * 8 + (lane & 3) * 2;
            const float2 b2 = *(const float2*)(bias + c);
            float2 o0 = { acc[i][j][0] + b2.x, acc[i][j][1] + b2.y };
            float2 o1 = { acc[i][j][2] + b2.x, acc[i][j][3] + b2.y };
            *(float2*)(C + (size_t)r0 * N + c) = o0;
            *(float2*)(C + (size_t)(r0 + 8) * N + c) = o1;
        }
    }
}

// ================= HMMA fused flash attention with edge bias =================
// grid (8, 64), 256 threads = 8 warps; warp w owns q-rows [16w, 16w+16).
// BKV = 64. S and O live in registers. hi/lo bf16 split, 3 products.
#define QP 72                          /* bf16 pitch (144 B rows, conflict-free ldmatrix) */
#define QH_OFF 0
#define QL_OFF (128*QP*2)              /* 18432 */
#define KH_OFF (2*128*QP*2)            /* 36864 */
#define KL_OFF (KH_OFF + 64*QP*2)      /* +9216 */
#define VH_OFF (KL_OFF + 64*QP*2)
#define VL_OFF (VH_OFF + 64*QP*2)
#define BIAS_OFF (VL_OFF + 64*QP*2)    /* 73728 */
#define BIASP 65
#define ET_OFF (BIAS_OFF + 128*BIASP*4) /* 107008 */
#define ATTN_SMEM (ET_OFF + 64)

__global__ __launch_bounds__(256) void attn_hmma(
    const float* __restrict__ attn_mask,
    const unsigned char* __restrict__ kpm,
    const float* __restrict__ edge_tab)
{
    extern __shared__ char smc[];
    const uint32_t sb = cvta_smem(smc);
    float* biasS = (float*)(smc + BIAS_OFF);
    float* etp   = (float*)(smc + ET_OFF);

    const int t = threadIdx.x, w = t >> 5, lane = t & 31;
    const int qb = blockIdx.x, bh = blockIdx.y;
    const int b = bh >> 3, h = bh & 7;
    const int q0 = qb << 7;
    const size_t edge_base = (size_t)b << 20;

    if (t < 16) etp[t] = edge_tab[t * H_ + h];

    // ---- stage Q (once): rows t>>1, col half (t&1)*32 ----
    {
        const int r = t >> 1, c0 = (t & 1) << 5;
        const float* src = g_qkv + (size_t)((q0 + r) * B_ + b) * QKV_LD + h * D_ + c0;
        char* qh = smc + QH_OFF + (r * QP + c0) * 2;
        char* ql = smc + QL_OFF + (r * QP + c0) * 2;
#pragma unroll
        for (int q = 0; q < 8; q++) {
            uint2 hi, lo;
            split4(*(const float4*)(src + q * 4), hi, lo);
            *(uint2*)(qh + q * 8) = hi;
            *(uint2*)(ql + q * 8) = lo;
        }
    }

    float o[8][4];
#pragma unroll
    for (int j = 0; j < 8; j++)
#pragma unroll
        for (int c = 0; c < 4; c++) o[j][c] = 0.f;
    float m0p = -1e30f, m1p = -1e30f, l0 = 0.f, l1 = 0.f;

    // ldmatrix lane addr components
    const uint32_t a_row = (uint32_t)((lane & 7) + ((lane >> 3) & 1) * 8);
    const uint32_t a_kb  = (uint32_t)((lane >> 4) << 4);
    const uint32_t b_row = (uint32_t)(lane & 7);
    const uint32_t b_kb  = (uint32_t)(((lane >> 3) & 1) << 4);
    const uint32_t v_row = (uint32_t)(lane & 15);

    for (int kb = 0; kb < 16; kb++) {
        const int m0 = kb << 6;
        if (kb) __syncthreads();     // prior compute done before restaging

        // ---- stage K,V tiles [64 x 64] hi/lo ----
        {
            const int r = t >> 2, c0 = (t & 3) << 4;
            const float* kq = g_qkv + (size_t)((m0 + r) * B_ + b) * QKV_LD + E_ + h * D_ + c0;
            char* kh = smc + KH_OFF + (r * QP + c0) * 2;
            char* kl = smc + KL_OFF + (r * QP + c0) * 2;
            char* vh = smc + VH_OFF + (r * QP + c0) * 2;
            char* vl = smc + VL_OFF + (r * QP + c0) * 2;
#pragma unroll
            for (int q = 0; q < 4; q++) {
                uint2 hi, lo;
                split4(*(const float4*)(kq + q * 4), hi, lo);
                *(uint2*)(kh + q * 8) = hi; *(uint2*)(kl + q * 8) = lo;
                split4(*(const float4*)(kq + E_ + q * 4), hi, lo);
                *(uint2*)(vh + q * 8) = hi; *(uint2*)(vl + q * 8) = lo;
            }
        }
        // ---- stage bias tile [128 x 64] = mask + edge-bias + key-padding ----
        {
            const int i = t >> 1, c0 = (t & 1) << 5;
            const int qi = q0 + i;
            const float* mp = attn_mask + (size_t)qi * L_ + m0 + c0;
            union { uint4 u[2]; unsigned char c[32]; } eu, ku;
            eu.u[0] = *(const uint4*)(g_edge8 + edge_base + (size_t)qi * L_ + m0 + c0);
            eu.u[1] = *(const uint4*)(g_edge8 + edge_base + (size_t)qi * L_ + m0 + c0 + 16);
            ku.u[0] = *(const uint4*)(kpm + b * L_ + m0 + c0);
            ku.u[1] = *(const uint4*)(kpm + b * L_ + m0 + c0 + 16);
            float* bo = biasS + i * BIASP + c0;
#pragma unroll
            for (int q = 0; q < 8; q++) {
                const float4 mv = *(const float4*)(mp + q * 4);
#pragma unroll
                for (int e = 0; e < 4; e++) {
                    const int idx = q * 4 + e;
                    const float mval = (e == 0) ? mv.x : (e == 1) ? mv.y : (e == 2) ? mv.z : mv.w;
                    bo[idx] = mval + etp[eu.c[idx]] + (ku.c[idx] ? -1e30f : 0.f);
                }
            }
        }
        __syncthreads();

        // ---- S = Q K^T (per warp: 16 x 64), hi/lo 3 products ----
        float sacc[8][4];
#pragma unroll
        for (int j = 0; j < 8; j++)
#pragma unroll
            for (int c = 0; c < 4; c++) sacc[j][c] = 0.f;
#pragma unroll
        for (int kk = 0; kk < 4; kk++) {
            uint32_t qh[4], ql[4];
            const uint32_t qr = (uint32_t)(w * 16) + a_row;
            const uint32_t qa = sb + QH_OFF + qr * (QP*2) + (uint32_t)(kk * 32) + a_kb;
            ldsm4(qh[0], qh[1], qh[2], qh[3], qa);
            ldsm4(ql[0], ql[1], ql[2], ql[3], qa + (QL_OFF - QH_OFF));
#pragma unroll
            for (int j = 0; j < 8; j++) {
                const uint32_t kr = (uint32_t)(j * 8) + b_row;
                const uint32_t ka = sb + KH_OFF + kr * (QP*2) + (uint32_t)(kk * 32) + b_kb;
                uint32_t kh0, kh1, kl0, kl1;
                ldsm2(kh0, kh1, ka);
                ldsm2(kl0, kl1, ka + (KL_OFF - KH_OFF));
                mma_bf16(sacc[j][0], sacc[j][1], sacc[j][2], sacc[j][3],
                         qh[0], qh[1], qh[2], qh[3], kh0, kh1);
                mma_bf16(sacc[j][0], sacc[j][1], sacc[j][2], sacc[j][3],
                         qh[0], qh[1], qh[2], qh[3], kl0, kl1);
                mma_bf16(sacc[j][0], sacc[j][1], sacc[j][2], sacc[j][3],
                         ql[0], ql[1], ql[2], ql[3], kh0, kh1);
            }
        }
        // ---- epilogue: scale + bias ----
        {
            const int rl = w * 16 + (lane >> 2);
            const float* bi0 = biasS + rl * BIASP;
            const float* bi1 = biasS + (rl + 8) * BIASP;
#pragma unroll
            for (int j = 0; j < 8; j++) {
                const int c = j * 8 + (lane & 3) * 2;
                sacc[j][0] = sacc[j][0] * 0.125f + bi0[c];
                sacc[j][1] = sacc[j][1] * 0.125f + bi0[c + 1];
                sacc[j][2] = sacc[j][2] * 0.125f + bi1[c];
                sacc[j][3] = sacc[j][3] * 0.125f + bi1[c + 1];
            }
        }
        // ---- online softmax (rows rl, rl+8) ----
        float mx0 = -1e30f, mx1 = -1e30f;
#pragma unroll
        for (int j = 0; j < 8; j++) {
            mx0 = fmaxf(mx0, fmaxf(sacc[j][0], sacc[j][1]));
            mx1 = fmaxf(mx1, fmaxf(sacc[j][2], sacc[j][3]));
        }
        mx0 = fmaxf(mx0, __shfl_xor_sync(0xffffffffu, mx0, 1));
        mx0 = fmaxf(mx0, __shfl_xor_sync(0xffffffffu, mx0, 2));
        mx1 = fmaxf(mx1, __shfl_xor_sync(0xffffffffu, mx1, 1));
        mx1 = fmaxf(mx1, __shfl_xor_sync(0xffffffffu, mx1, 2));
        const float mn0 = fmaxf(m0p, mx0), mn1 = fmaxf(m1p, mx1);
        const float c0 = __expf(m0p - mn0), c1 = __expf(m1p - mn1);
        m0p = mn0; m1p = mn1;
        float s0 = 0.f, s1 = 0.f;
#pragma unroll
        for (int j = 0; j < 8; j++) {
            sacc[j][0] = __expf(sacc[j][0] - mn0); s0 += sacc[j][0];
            sacc[j][1] = __expf(sacc[j][1] - mn0); s0 += sacc[j][1];
            sacc[j][2] = __expf(sacc[j][2] - mn1); s1 += sacc[j][2];
            sacc[j][3] = __expf(sacc[j][3] - mn1); s1 += sacc[j][3];
        }
        s0 += __shfl_xor_sync(0xffffffffu, s0, 1);
        s0 += __shfl_xor_sync(0xffffffffu, s0, 2);
        s1 += __shfl_xor_sync(0xffffffffu, s1, 1);
        s1 += __shfl_xor_sync(0xffffffffu, s1, 2);
        l0 = l0 * c0 + s0;
        l1 = l1 * c1 + s1;
#pragma unroll
        for (int j = 0; j < 8; j++) {
            o[j][0] *= c0; o[j][1] *= c0; o[j][2] *= c1; o[j][3] *= c1;
        }

        // ---- O += P V : P from regs (repack C-frag as A-frags), V via ldmatrix.trans ----
#pragma unroll
        for (int kk = 0; kk < 4; kk++) {
            uint32_t ph[4], pl[4];
#pragma unroll
            for (int half = 0; half < 2; half++) {
                const int jt = 2 * kk + half;
                const float p0 = sacc[jt][0], p1 = sacc[jt][1];
                const float p2 = sacc[jt][2], p3 = sacc[jt][3];
                const __nv_bfloat16 h0 = __float2bfloat16(p0), h1 = __float2bfloat16(p1);
                const __nv_bfloat16 h2 = __float2bfloat16(p2), h3 = __float2bfloat16(p3);
                ph[2*half + 0] = pack2h(h0, h1);
                ph[2*half + 1] = pack2h(h2, h3);
                pl[2*half + 0] = packbf(p0 - __bfloat162float(h0), p1 - __bfloat162float(h1));
                pl[2*half + 1] = packbf(p2 - __bfloat162float(h2), p3 - __bfloat162float(h3));
            }
#pragma unroll
            for (int j = 0; j < 8; j++) {
                const uint32_t vr = (uint32_t)(kk * 16) + v_row;
                const uint32_t va = sb + VH_OFF + vr * (QP*2) + (uint32_t)(j * 16);
                uint32_t vh0, vh1, vl0, vl1;
                ldsm2t(vh0, vh1, va);
                ldsm2t(vl0, vl1, va + (VL_OFF - VH_OFF));
                mma_bf16(o[j][0], o[j][1], o[j][2], o[j][3],
                         ph[0], ph[1], ph[2], ph[3], vh0, vh1);
                mma_bf16(o[j][0], o[j][1], o[j][2], o[j][3],
                         ph[0], ph[1], ph[2], ph[3], vl0, vl1);
                mma_bf16(o[j][0], o[j][1], o[j][2], o[j][3],
                         pl[0], pl[1], pl[2], pl[3], vh0, vh1);
            }
        }
    }

    // ---- normalize and write [L,B,H,D] ----
    {
        const float inv0 = 1.f / l0, inv1 = 1.f / l1;
        const int gr0 = q0 + w * 16 + (lane >> 2);
#pragma unroll
        for (int j = 0; j < 8; j++) {
            const int c = h * D_ + j * 8 + (lane & 3) * 2;
            float2 w0 = { o[j][0] * inv0, o[j][1] * inv0 };
            float2 w1 = { o[j][2] * inv1, o[j][3] * inv1 };
            *(float2*)(g_att + (size_t)(gr0 * B_ + b) * E_ + c) = w0;
            *(float2*)(g_att + (size_t)((gr0 + 8) * B_ + b) * E_ + c) = w1;
        }
    }
}

// ---------------- launch ----------------
extern "C" void kernel_launch(void* const* d_in, const int* in_sizes, int n_in,
                              void* d_out, int out_size)
{
    const float*         x         = (const float*)d_in[0];
    const void*          edge      = d_in[1];
    const float*         attn_mask = (const float*)d_in[2];
    const unsigned char* kpm       = (const unsigned char*)d_in[3];
    const float*         in_w      = (const float*)d_in[4];
    const float*         in_b      = (const float*)d_in[5];
    const float*         out_w     = (const float*)d_in[6];
    const float*         out_b     = (const float*)d_in[7];
    const float*         edge_tab  = (const float*)d_in[8];
    float* out = (float*)d_out;

    float *qkv_ptr = nullptr, *att_ptr = nullptr;
    cudaGetSymbolAddress((void**)&qkv_ptr, g_qkv);
    cudaGetSymbolAddress((void**)&att_ptr, g_att);

    cudaFuncSetAttribute(gemm_hmma, cudaFuncAttributeMaxDynamicSharedMemorySize, GEMM_SMEM);
    cudaFuncSetAttribute(attn_hmma, cudaFuncAttributeMaxDynamicSharedMemorySize, ATTN_SMEM);

    // detect edge dtype (values < 16 -> int64 odd words all zero)
    detect_edge_dtype_kernel<<<1, 32>>>((const unsigned int*)edge);
    // pack edge -> uint8
    pack_edge_kernel<<<(B_ * L_ * L_) / (256 * 4), 256>>>(edge);

    // QKV projection: [8192,1536] = x @ in_w^T + in_b
    gemm_hmma<<<dim3(QKV_LD / 128, ROWS_ / 128), 256, GEMM_SMEM>>>(
        x, in_w, in_b, qkv_ptr, QKV_LD, E_);

    // fused attention
    attn_hmma<<<dim3(L_ / 128, B_ * H_), 256, ATTN_SMEM>>>(attn_mask, kpm, edge_tab);

    // output projection: [8192,512] = g_att @ out_w^T + out_b
    gemm_hmma<<<dim3(E_ / 128, ROWS_ / 128), 256, GEMM_SMEM>>>(
        att_ptr, out_w, out_b, out, E_, E_);
}

// round 5
// speedup vs baseline: 2.3060x; 1.1783x over previous
#include <cuda_runtime.h>
#include <cuda_bf16.h>
#include <cstdint>

#define L_ 1024
#define B_ 8
#define E_ 512
#define H_ 8
#define D_ 64
#define ROWS_ (L_*B_)          /* 8192 */
#define QKV_LD (3*E_)          /* 1536 */

// ---------------- scratch (no cudaMalloc allowed) ----------------
__device__ float g_qkv[(size_t)ROWS_ * QKV_LD];         // 50.3 MB
__device__ float g_att[(size_t)ROWS_ * E_];             // 16.8 MB
__device__ unsigned char g_edge8[(size_t)B_ * L_ * L_]; // 8.4 MB
__device__ int g_is64;

// ================= helpers (plain sm_103-safe: mma.sync + ldmatrix) =================
__device__ __forceinline__ uint32_t cvta_smem(const void* p) {
    uint32_t a;
    asm("{ .reg .u64 t; cvta.to.shared.u64 t, %1; cvt.u32.u64 %0, t; }" : "=r"(a) : "l"(p));
    return a;
}
__device__ __forceinline__ void ldsm4(uint32_t& r0, uint32_t& r1, uint32_t& r2, uint32_t& r3, uint32_t a) {
    asm volatile("ldmatrix.sync.aligned.m8n8.x4.shared.b16 {%0,%1,%2,%3}, [%4];"
                 : "=r"(r0), "=r"(r1), "=r"(r2), "=r"(r3) : "r"(a));
}
__device__ __forceinline__ void ldsm4t(uint32_t& r0, uint32_t& r1, uint32_t& r2, uint32_t& r3, uint32_t a) {
    asm volatile("ldmatrix.sync.aligned.m8n8.x4.trans.shared.b16 {%0,%1,%2,%3}, [%4];"
                 : "=r"(r0), "=r"(r1), "=r"(r2), "=r"(r3) : "r"(a));
}
__device__ __forceinline__ void mma_bf16(float& d0, float& d1, float& d2, float& d3,
                                         uint32_t a0, uint32_t a1, uint32_t a2, uint32_t a3,
                                         uint32_t b0, uint32_t b1) {
    asm volatile("mma.sync.aligned.m16n8k16.row.col.f32.bf16.bf16.f32 "
                 "{%0,%1,%2,%3}, {%4,%5,%6,%7}, {%8,%9}, {%0,%1,%2,%3};"
                 : "+f"(d0), "+f"(d1), "+f"(d2), "+f"(d3)
                 : "r"(a0), "r"(a1), "r"(a2), "r"(a3), "r"(b0), "r"(b1));
}
__device__ __forceinline__ uint32_t pack2h(__nv_bfloat16 a, __nv_bfloat16 b) {
    return (uint32_t)__bfloat16_as_ushort(a) | ((uint32_t)__bfloat16_as_ushort(b) << 16);
}
__device__ __forceinline__ uint32_t packbf(float x, float y) {
    return pack2h(__float2bfloat16(x), __float2bfloat16(y));
}
__device__ __forceinline__ void split4(const float4 v, uint2& hi, uint2& lo) {
    __nv_bfloat16 h0 = __float2bfloat16(v.x), h1 = __float2bfloat16(v.y);
    __nv_bfloat16 h2 = __float2bfloat16(v.z), h3 = __float2bfloat16(v.w);
    hi.x = pack2h(h0, h1); hi.y = pack2h(h2, h3);
    lo.x = packbf(v.x - __bfloat162float(h0), v.y - __bfloat162float(h1));
    lo.y = packbf(v.z - __bfloat162float(h2), v.w - __bfloat162float(h3));
}

// ---------------- kernel -1: detect edge dtype (int32 vs int64) ----------------
__global__ void detect_edge_dtype_kernel(const unsigned int* __restrict__ e)
{
    const int t = threadIdx.x;
    unsigned v = 0;
    for (int i = t; i < 512; i += 32) v |= e[2 * i + 1];
    const unsigned any = __ballot_sync(0xffffffffu, v != 0u);
    if (t == 0) g_is64 = (any == 0u) ? 1 : 0;
}

// ---------------- kernel 0: pack edge (int32 or int64) -> uint8 ----------------
__global__ __launch_bounds__(256) void pack_edge_kernel(const void* __restrict__ edge)
{
    const int i = blockIdx.x * blockDim.x + threadIdx.x;
    uchar4 u;
    if (g_is64) {
        const long long* e = (const long long*)edge;
        u.x = (unsigned char)e[(size_t)i*4 + 0];
        u.y = (unsigned char)e[(size_t)i*4 + 1];
        u.z = (unsigned char)e[(size_t)i*4 + 2];
        u.w = (unsigned char)e[(size_t)i*4 + 3];
    } else {
        const int4 v = *(const int4*)((const int*)edge + (size_t)i*4);
        u.x = (unsigned char)v.x; u.y = (unsigned char)v.y;
        u.z = (unsigned char)v.z; u.w = (unsigned char)v.w;
    }
    *(uchar4*)(g_edge8 + (size_t)i*4) = u;
}

// ================= HMMA GEMM: C[M,N] = A[M,K]·B[N,K]^T + bias =================
// fp32 -> bf16 hi/lo split at staging; 3 mma products (hh + hl + lh).
// BM=BN=128, BK=32, 256 threads = 8 warps as 4(m)x2(n), warp tile 32x64.
// Single-buffered stage; occupancy 2 CTAs/SM hides latency across CTAs.
#define GP 40                         /* bf16 pitch for 32-col tiles */
#define GTILE (128*GP*2)              /* 10240 B per tile */
#define GEMM_SMEM (4*GTILE)           /* Ah, Al, Bh, Bl = 40960 B */

__global__ __launch_bounds__(256, 2) void gemm_hmma(
    const float* __restrict__ A, const float* __restrict__ Bm,
    const float* __restrict__ bias, float* __restrict__ C,
    int N, int K)
{
    extern __shared__ char smc[];
    const uint32_t sb = cvta_smem(smc);
    const int t = threadIdx.x, wid = t >> 5, lane = t & 31;
    const int wm = wid & 3, wn = wid >> 2;
    const int bm = blockIdx.y << 7, bn = blockIdx.x << 7;

    const int row = t >> 1, kc = (t & 1) << 4;
    const float* Ap = A  + (size_t)(bm + row) * K + kc;
    const float* Bp = Bm + (size_t)(bn + row) * K + kc;
    const uint32_t stoff = (uint32_t)(row * GP + kc) * 2;

    float acc[2][8][4];
#pragma unroll
    for (int i = 0; i < 2; i++)
#pragma unroll
        for (int j = 0; j < 8; j++)
#pragma unroll
            for (int c = 0; c < 4; c++) acc[i][j][c] = 0.f;

    // ldmatrix lane addressing
    const uint32_t a_row = (uint32_t)((lane & 7) + ((lane >> 3) & 1) * 8);
    const uint32_t a_kb  = (uint32_t)((lane >> 4) << 4);
    const uint32_t p_row = (uint32_t)((lane & 7) + ((lane >> 4) & 1) * 8);  // pair-B rows
    const uint32_t p_kb  = (uint32_t)(((lane >> 3) & 1) << 4);

    const int niter = K >> 5;
    for (int it = 0; it < niter; it++) {
        if (it) __syncthreads();
        {
            const float* ap = Ap + it * 32;
            const float* bp = Bp + it * 32;
            char* s = smc + stoff;
#pragma unroll
            for (int j = 0; j < 4; j++) {
                uint2 hi, lo;
                split4(*(const float4*)(ap + j*4), hi, lo);
                *(uint2*)(s + j*8) = hi;
                *(uint2*)(s + GTILE + j*8) = lo;
                split4(*(const float4*)(bp + j*4), hi, lo);
                *(uint2*)(s + 2*GTILE + j*8) = hi;
                *(uint2*)(s + 3*GTILE + j*8) = lo;
            }
        }
        __syncthreads();
#pragma unroll
        for (int kk = 0; kk < 2; kk++) {
            uint32_t ah[2][4], al[2][4];
#pragma unroll
            for (int i = 0; i < 2; i++) {
                const uint32_t ad = sb + (uint32_t)(wm * 32 + i * 16 + a_row) * (GP*2)
                                  + (uint32_t)(kk * 32) + a_kb;
                ldsm4(ah[i][0], ah[i][1], ah[i][2], ah[i][3], ad);
                ldsm4(al[i][0], al[i][1], al[i][2], al[i][3], ad + GTILE);
            }
#pragma unroll
            for (int jp = 0; jp < 4; jp++) {
                const uint32_t bd = sb + 2*GTILE + (uint32_t)(wn * 64 + jp * 16 + p_row) * (GP*2)
                                  + (uint32_t)(kk * 32) + p_kb;
                uint32_t bh0, bh1, bh2, bh3, bl0, bl1, bl2, bl3;
                ldsm4(bh0, bh1, bh2, bh3, bd);
                ldsm4(bl0, bl1, bl2, bl3, bd + GTILE);
#pragma unroll
                for (int i = 0; i < 2; i++) {
                    float* a0 = acc[i][2*jp];
                    float* a1 = acc[i][2*jp+1];
                    mma_bf16(a0[0], a0[1], a0[2], a0[3], ah[i][0], ah[i][1], ah[i][2], ah[i][3], bh0, bh1);
                    mma_bf16(a0[0], a0[1], a0[2], a0[3], ah[i][0], ah[i][1], ah[i][2], ah[i][3], bl0, bl1);
                    mma_bf16(a0[0], a0[1], a0[2], a0[3], al[i][0], al[i][1], al[i][2], al[i][3], bh0, bh1);
                    mma_bf16(a1[0], a1[1], a1[2], a1[3], ah[i][0], ah[i][1], ah[i][2], ah[i][3], bh2, bh3);
                    mma_bf16(a1[0], a1[1], a1[2], a1[3], ah[i][0], ah[i][1], ah[i][2], ah[i][3], bl2, bl3);
                    mma_bf16(a1[0], a1[1], a1[2], a1[3], al[i][0], al[i][1], al[i][2], al[i][3], bh2, bh3);
                }
            }
        }
    }

    // epilogue
#pragma unroll
    for (int i = 0; i < 2; i++) {
        const int r0 = bm + wm * 32 + i * 16 + (lane >> 2);
#pragma unroll
        for (int j = 0; j < 8; j++) {
            const int c = bn + wn * 64 + j * 8 + (lane & 3) * 2;
            const float2 b2 = *(const float2*)(bias + c);
            float2 o0 = { acc[i][j][0] + b2.x, acc[i][j][1] + b2.y };
            float2 o1 = { acc[i][j][2] + b2.x, acc[i][j][3] + b2.y };
            *(float2*)(C + (size_t)r0 * N + c) = o0;
            *(float2*)(C + (size_t)(r0 + 8) * N + c) = o1;
        }
    }
}

// ================= HMMA fused flash attention with edge bias =================
// grid (8, 64), 256 threads = 8 warps; warp w owns q-rows [16w, 16w+16).
// BKV = 64. S and O live in registers. hi/lo bf16 split, 3 products.
#define QP 72                          /* bf16 pitch (144 B rows, conflict-free ldmatrix) */
#define QH_OFF 0
#define QL_OFF (128*QP*2)              /* 18432 */
#define KH_OFF (2*128*QP*2)            /* 36864 */
#define KL_OFF (KH_OFF + 64*QP*2)
#define VH_OFF (KL_OFF + 64*QP*2)
#define VL_OFF (VH_OFF + 64*QP*2)
#define BIAS_OFF (VL_OFF + 64*QP*2)    /* 73728 */
#define BIASP 65
#define ET_OFF (BIAS_OFF + 128*BIASP*4) /* 107008 */
#define ATTN_SMEM (ET_OFF + 64)

__global__ __launch_bounds__(256, 2) void attn_hmma(
    const float* __restrict__ attn_mask,
    const unsigned char* __restrict__ kpm,
    const float* __restrict__ edge_tab)
{
    extern __shared__ char smc[];
    const uint32_t sb = cvta_smem(smc);
    float* biasS = (float*)(smc + BIAS_OFF);
    float* etp   = (float*)(smc + ET_OFF);

    const int t = threadIdx.x, w = t >> 5, lane = t & 31;
    const int qb = blockIdx.x, bh = blockIdx.y;
    const int b = bh >> 3, h = bh & 7;
    const int q0 = qb << 7;
    const size_t edge_base = (size_t)b << 20;

    if (t < 16) etp[t] = edge_tab[t * H_ + h];

    // ---- stage Q (once) ----
    {
        const int r = t >> 1, c0 = (t & 1) << 5;
        const float* src = g_qkv + (size_t)((q0 + r) * B_ + b) * QKV_LD + h * D_ + c0;
        char* qh = smc + QH_OFF + (r * QP + c0) * 2;
        char* ql = smc + QL_OFF + (r * QP + c0) * 2;
#pragma unroll
        for (int q = 0; q < 8; q++) {
            uint2 hi, lo;
            split4(*(const float4*)(src + q * 4), hi, lo);
            *(uint2*)(qh + q * 8) = hi;
            *(uint2*)(ql + q * 8) = lo;
        }
    }

    float o[8][4];
#pragma unroll
    for (int j = 0; j < 8; j++)
#pragma unroll
        for (int c = 0; c < 4; c++) o[j][c] = 0.f;
    float m0p = -1e30f, m1p = -1e30f, l0 = 0.f, l1 = 0.f;

    // ldmatrix lane addr components
    const uint32_t a_row = (uint32_t)((lane & 7) + ((lane >> 3) & 1) * 8);
    const uint32_t a_kb  = (uint32_t)((lane >> 4) << 4);
    const uint32_t p_row = (uint32_t)((lane & 7) + ((lane >> 4) & 1) * 8);  // pair-B
    const uint32_t p_kb  = (uint32_t)(((lane >> 3) & 1) << 4);
    const uint32_t v_row = (uint32_t)(lane & 15);
    const uint32_t v_cb  = (uint32_t)((lane >> 4) << 4);                    // pair-V col byte

    for (int kb = 0; kb < 16; kb++) {
        const int m0 = kb << 6;
        if (kb) __syncthreads();

        // ---- stage K,V tiles [64 x 64] hi/lo ----
        {
            const int r = t >> 2, c0 = (t & 3) << 4;
            const float* kq = g_qkv + (size_t)((m0 + r) * B_ + b) * QKV_LD + E_ + h * D_ + c0;
            char* kh = smc + KH_OFF + (r * QP + c0) * 2;
#pragma unroll
            for (int q = 0; q < 4; q++) {
                uint2 hi, lo;
                split4(*(const float4*)(kq + q * 4), hi, lo);
                *(uint2*)(kh + q * 8) = hi;
                *(uint2*)(kh + (KL_OFF-KH_OFF) + q * 8) = lo;
                split4(*(const float4*)(kq + E_ + q * 4), hi, lo);
                *(uint2*)(kh + (VH_OFF-KH_OFF) + q * 8) = hi;
                *(uint2*)(kh + (VL_OFF-KH_OFF) + q * 8) = lo;
            }
        }
        // ---- stage bias tile [128 x 64] = mask + edge-bias + key-padding ----
        {
            const int i = t >> 1, c0 = (t & 1) << 5;
            const int qi = q0 + i;
            const float* mp = attn_mask + (size_t)qi * L_ + m0 + c0;
            union { uint4 u[2]; unsigned char c[32]; } eu, ku;
            eu.u[0] = *(const uint4*)(g_edge8 + edge_base + (size_t)qi * L_ + m0 + c0);
            eu.u[1] = *(const uint4*)(g_edge8 + edge_base + (size_t)qi * L_ + m0 + c0 + 16);
            ku.u[0] = *(const uint4*)(kpm + b * L_ + m0 + c0);
            ku.u[1] = *(const uint4*)(kpm + b * L_ + m0 + c0 + 16);
            float* bo = biasS + i * BIASP + c0;
#pragma unroll
            for (int q = 0; q < 8; q++) {
                const float4 mv = *(const float4*)(mp + q * 4);
#pragma unroll
                for (int e = 0; e < 4; e++) {
                    const int idx = q * 4 + e;
                    const float mval = (e == 0) ? mv.x : (e == 1) ? mv.y : (e == 2) ? mv.z : mv.w;
                    bo[idx] = mval + etp[eu.c[idx]] + (ku.c[idx] ? -1e30f : 0.f);
                }
            }
        }
        __syncthreads();

        // ---- S = Q K^T (per warp: 16 x 64), hi/lo 3 products, K in j-pairs ----
        float sacc[8][4];
#pragma unroll
        for (int j = 0; j < 8; j++)
#pragma unroll
            for (int c = 0; c < 4; c++) sacc[j][c] = 0.f;
#pragma unroll
        for (int kk = 0; kk < 4; kk++) {
            uint32_t qh[4], ql[4];
            const uint32_t qa = sb + QH_OFF + (uint32_t)(w * 16 + a_row) * (QP*2)
                              + (uint32_t)(kk * 32) + a_kb;
            ldsm4(qh[0], qh[1], qh[2], qh[3], qa);
            ldsm4(ql[0], ql[1], ql[2], ql[3], qa + (QL_OFF - QH_OFF));
#pragma unroll
            for (int jp = 0; jp < 4; jp++) {
                const uint32_t ka = sb + KH_OFF + (uint32_t)(jp * 16 + p_row) * (QP*2)
                                  + (uint32_t)(kk * 32) + p_kb;
                uint32_t kh0, kh1, kh2, kh3, kl0, kl1, kl2, kl3;
                ldsm4(kh0, kh1, kh2, kh3, ka);
                ldsm4(kl0, kl1, kl2, kl3, ka + (KL_OFF - KH_OFF));
                float* s0 = sacc[2*jp];
                float* s1 = sacc[2*jp+1];
                mma_bf16(s0[0], s0[1], s0[2], s0[3], qh[0], qh[1], qh[2], qh[3], kh0, kh1);
                mma_bf16(s0[0], s0[1], s0[2], s0[3], qh[0], qh[1], qh[2], qh[3], kl0, kl1);
                mma_bf16(s0[0], s0[1], s0[2], s0[3], ql[0], ql[1], ql[2], ql[3], kh0, kh1);
                mma_bf16(s1[0], s1[1], s1[2], s1[3], qh[0], qh[1], qh[2], qh[3], kh2, kh3);
                mma_bf16(s1[0], s1[1], s1[2], s1[3], qh[0], qh[1], qh[2], qh[3], kl2, kl3);
                mma_bf16(s1[0], s1[1], s1[2], s1[3], ql[0], ql[1], ql[2], ql[3], kh2, kh3);
            }
        }
        // ---- epilogue: scale + bias ----
        {
            const int rl = w * 16 + (lane >> 2);
            const float* bi0 = biasS + rl * BIASP;
            const float* bi1 = biasS + (rl + 8) * BIASP;
#pragma unroll
            for (int j = 0; j < 8; j++) {
                const int c = j * 8 + (lane & 3) * 2;
                sacc[j][0] = sacc[j][0] * 0.125f + bi0[c];
                sacc[j][1] = sacc[j][1] * 0.125f + bi0[c + 1];
                sacc[j][2] = sacc[j][2] * 0.125f + bi1[c];
                sacc[j][3] = sacc[j][3] * 0.125f + bi1[c + 1];
            }
        }
        // ---- online softmax ----
        float mx0 = -1e30f, mx1 = -1e30f;
#pragma unroll
        for (int j = 0; j < 8; j++) {
            mx0 = fmaxf(mx0, fmaxf(sacc[j][0], sacc[j][1]));
            mx1 = fmaxf(mx1, fmaxf(sacc[j][2], sacc[j][3]));
        }
        mx0 = fmaxf(mx0, __shfl_xor_sync(0xffffffffu, mx0, 1));
        mx0 = fmaxf(mx0, __shfl_xor_sync(0xffffffffu, mx0, 2));
        mx1 = fmaxf(mx1, __shfl_xor_sync(0xffffffffu, mx1, 1));
        mx1 = fmaxf(mx1, __shfl_xor_sync(0xffffffffu, mx1, 2));
        const float mn0 = fmaxf(m0p, mx0), mn1 = fmaxf(m1p, mx1);
        const float c0 = __expf(m0p - mn0), c1 = __expf(m1p - mn1);
        m0p = mn0; m1p = mn1;
        float s0 = 0.f, s1 = 0.f;
#pragma unroll
        for (int j = 0; j < 8; j++) {
            sacc[j][0] = __expf(sacc[j][0] - mn0); s0 += sacc[j][0];
            sacc[j][1] = __expf(sacc[j][1] - mn0); s0 += sacc[j][1];
            sacc[j][2] = __expf(sacc[j][2] - mn1); s1 += sacc[j][2];
            sacc[j][3] = __expf(sacc[j][3] - mn1); s1 += sacc[j][3];
        }
        s0 += __shfl_xor_sync(0xffffffffu, s0, 1);
        s0 += __shfl_xor_sync(0xffffffffu, s0, 2);
        s1 += __shfl_xor_sync(0xffffffffu, s1, 1);
        s1 += __shfl_xor_sync(0xffffffffu, s1, 2);
        l0 = l0 * c0 + s0;
        l1 = l1 * c1 + s1;
#pragma unroll
        for (int j = 0; j < 8; j++) {
            o[j][0] *= c0; o[j][1] *= c0; o[j][2] *= c1; o[j][3] *= c1;
        }

        // ---- O += P V : P from regs, V via ldmatrix.x4.trans (j-pairs) ----
#pragma unroll
        for (int kk = 0; kk < 4; kk++) {
            uint32_t ph[4], pl[4];
#pragma unroll
            for (int half = 0; half < 2; half++) {
                const int jt = 2 * kk + half;
                const float p0 = sacc[jt][0], p1 = sacc[jt][1];
                const float p2 = sacc[jt][2], p3 = sacc[jt][3];
                const __nv_bfloat16 h0 = __float2bfloat16(p0), h1 = __float2bfloat16(p1);
                const __nv_bfloat16 h2 = __float2bfloat16(p2), h3 = __float2bfloat16(p3);
                ph[2*half + 0] = pack2h(h0, h1);
                ph[2*half + 1] = pack2h(h2, h3);
                pl[2*half + 0] = packbf(p0 - __bfloat162float(h0), p1 - __bfloat162float(h1));
                pl[2*half + 1] = packbf(p2 - __bfloat162float(h2), p3 - __bfloat162float(h3));
            }
#pragma unroll
            for (int jp = 0; jp < 4; jp++) {
                const uint32_t va = sb + VH_OFF + (uint32_t)(kk * 16 + v_row) * (QP*2)
                                  + (uint32_t)(jp * 32) + v_cb;
                uint32_t vh0, vh1, vh2, vh3, vl0, vl1, vl2, vl3;
                ldsm4t(vh0, vh1, vh2, vh3, va);
                ldsm4t(vl0, vl1, vl2, vl3, va + (VL_OFF - VH_OFF));
                float* o0 = o[2*jp];
                float* o1 = o[2*jp+1];
                mma_bf16(o0[0], o0[1], o0[2], o0[3], ph[0], ph[1], ph[2], ph[3], vh0, vh1);
                mma_bf16(o0[0], o0[1], o0[2], o0[3], ph[0], ph[1], ph[2], ph[3], vl0, vl1);
                mma_bf16(o0[0], o0[1], o0[2], o0[3], pl[0], pl[1], pl[2], pl[3], vh0, vh1);
                mma_bf16(o1[0], o1[1], o1[2], o1[3], ph[0], ph[1], ph[2], ph[3], vh2, vh3);
                mma_bf16(o1[0], o1[1], o1[2], o1[3], ph[0], ph[1], ph[2], ph[3], vl2, vl3);
                mma_bf16(o1[0], o1[1], o1[2], o1[3], pl[0], pl[1], pl[2], pl[3], vh2, vh3);
            }
        }
    }

    // ---- normalize and write [L,B,H,D] ----
    {
        const float inv0 = 1.f / l0, inv1 = 1.f / l1;
        const int gr0 = q0 + w * 16 + (lane >> 2);
#pragma unroll
        for (int j = 0; j < 8; j++) {
            const int c = h * D_ + j * 8 + (lane & 3) * 2;
            float2 w0 = { o[j][0] * inv0, o[j][1] * inv0 };
            float2 w1 = { o[j][2] * inv1, o[j][3] * inv1 };
            *(float2*)(g_att + (size_t)(gr0 * B_ + b) * E_ + c) = w0;
            *(float2*)(g_att + (size_t)((gr0 + 8) * B_ + b) * E_ + c) = w1;
        }
    }
}

// ---------------- launch ----------------
extern "C" void kernel_launch(void* const* d_in, const int* in_sizes, int n_in,
                              void* d_out, int out_size)
{
    const float*         x         = (const float*)d_in[0];
    const void*          edge      = d_in[1];
    const float*         attn_mask = (const float*)d_in[2];
    const unsigned char* kpm       = (const unsigned char*)d_in[3];
    const float*         in_w      = (const float*)d_in[4];
    const float*         in_b      = (const float*)d_in[5];
    const float*         out_w     = (const float*)d_in[6];
    const float*         out_b     = (const float*)d_in[7];
    const float*         edge_tab  = (const float*)d_in[8];
    float* out = (float*)d_out;

    float *qkv_ptr = nullptr, *att_ptr = nullptr;
    cudaGetSymbolAddress((void**)&qkv_ptr, g_qkv);
    cudaGetSymbolAddress((void**)&att_ptr, g_att);

    cudaFuncSetAttribute(gemm_hmma, cudaFuncAttributeMaxDynamicSharedMemorySize, GEMM_SMEM);
    cudaFuncSetAttribute(attn_hmma, cudaFuncAttributeMaxDynamicSharedMemorySize, ATTN_SMEM);

    // detect edge dtype (values < 16 -> int64 odd words all zero)
    detect_edge_dtype_kernel<<<1, 32>>>((const unsigned int*)edge);
    // pack edge -> uint8
    pack_edge_kernel<<<(B_ * L_ * L_) / (256 * 4), 256>>>(edge);

    // QKV projection: [8192,1536] = x @ in_w^T + in_b
    gemm_hmma<<<dim3(QKV_LD / 128, ROWS_ / 128), 256, GEMM_SMEM>>>(
        x, in_w, in_b, qkv_ptr, QKV_LD, E_);

    // fused attention
    attn_hmma<<<dim3(L_ / 128, B_ * H_), 256, ATTN_SMEM>>>(attn_mask, kpm, edge_tab);

    // output projection: [8192,512] = g_att @ out_w^T + out_b
    gemm_hmma<<<dim3(E_ / 128, ROWS_ / 128), 256, GEMM_SMEM>>>(
        att_ptr, out_w, out_b, out, E_, E_);
}

// round 6
// speedup vs baseline: 2.4133x; 1.0465x over previous
#include <cuda_runtime.h>
#include <cuda_bf16.h>
#include <cstdint>

#define L_ 1024
#define B_ 8
#define E_ 512
#define H_ 8
#define D_ 64
#define ROWS_ (L_*B_)          /* 8192 */
#define QKV_LD (3*E_)          /* 1536 */

// ---------------- scratch (no cudaMalloc allowed) ----------------
__device__ __nv_bfloat16 g_qkvh[(size_t)ROWS_ * QKV_LD];   // 25.2 MB
__device__ __nv_bfloat16 g_qkvl[(size_t)ROWS_ * QKV_LD];   // 25.2 MB
__device__ __nv_bfloat16 g_atth[(size_t)ROWS_ * E_];       // 8.4 MB
__device__ __nv_bfloat16 g_attl[(size_t)ROWS_ * E_];       // 8.4 MB
__device__ __nv_bfloat16 g_xh[(size_t)ROWS_ * E_];
__device__ __nv_bfloat16 g_xl[(size_t)ROWS_ * E_];
__device__ __nv_bfloat16 g_iwh[(size_t)QKV_LD * E_];
__device__ __nv_bfloat16 g_iwl[(size_t)QKV_LD * E_];
__device__ __nv_bfloat16 g_owh[(size_t)E_ * E_];
__device__ __nv_bfloat16 g_owl[(size_t)E_ * E_];
__device__ unsigned char g_edge8[(size_t)B_ * L_ * L_];    // 8.4 MB
__device__ int g_is64;

// ================= helpers (plain sm_103-safe) =================
__device__ __forceinline__ uint32_t cvta_smem(const void* p) {
    uint32_t a;
    asm("{ .reg .u64 t; cvta.to.shared.u64 t, %1; cvt.u32.u64 %0, t; }" : "=r"(a) : "l"(p));
    return a;
}
__device__ __forceinline__ void ldsm4(uint32_t& r0, uint32_t& r1, uint32_t& r2, uint32_t& r3, uint32_t a) {
    asm volatile("ldmatrix.sync.aligned.m8n8.x4.shared.b16 {%0,%1,%2,%3}, [%4];"
                 : "=r"(r0), "=r"(r1), "=r"(r2), "=r"(r3) : "r"(a));
}
__device__ __forceinline__ void ldsm4t(uint32_t& r0, uint32_t& r1, uint32_t& r2, uint32_t& r3, uint32_t a) {
    asm volatile("ldmatrix.sync.aligned.m8n8.x4.trans.shared.b16 {%0,%1,%2,%3}, [%4];"
                 : "=r"(r0), "=r"(r1), "=r"(r2), "=r"(r3) : "r"(a));
}
__device__ __forceinline__ void mma_bf16(float& d0, float& d1, float& d2, float& d3,
                                         uint32_t a0, uint32_t a1, uint32_t a2, uint32_t a3,
                                         uint32_t b0, uint32_t b1) {
    asm volatile("mma.sync.aligned.m16n8k16.row.col.f32.bf16.bf16.f32 "
                 "{%0,%1,%2,%3}, {%4,%5,%6,%7}, {%8,%9}, {%0,%1,%2,%3};"
                 : "+f"(d0), "+f"(d1), "+f"(d2), "+f"(d3)
                 : "r"(a0), "r"(a1), "r"(a2), "r"(a3), "r"(b0), "r"(b1));
}
#define CP_ASYNC16(dst, src) \
    asm volatile("cp.async.cg.shared.global [%0], [%1], 16;" :: "r"((uint32_t)(dst)), "l"(src))
#define CP_COMMIT() asm volatile("cp.async.commit_group;" ::: "memory")
#define CP_WAIT0()  asm volatile("cp.async.wait_group 0;" ::: "memory")
#define CP_WAIT1()  asm volatile("cp.async.wait_group 1;" ::: "memory")

__device__ __forceinline__ uint32_t pack2h(__nv_bfloat16 a, __nv_bfloat16 b) {
    return (uint32_t)__bfloat16_as_ushort(a) | ((uint32_t)__bfloat16_as_ushort(b) << 16);
}
__device__ __forceinline__ uint32_t packbf(float x, float y) {
    return pack2h(__float2bfloat16(x), __float2bfloat16(y));
}
__device__ __forceinline__ void split2(float x, float y, uint32_t& hi, uint32_t& lo) {
    __nv_bfloat16 h0 = __float2bfloat16(x), h1 = __float2bfloat16(y);
    hi = pack2h(h0, h1);
    lo = packbf(x - __bfloat162float(h0), y - __bfloat162float(h1));
}
__device__ __forceinline__ void split4(const float4 v, uint2& hi, uint2& lo) {
    split2(v.x, v.y, hi.x, lo.x);
    split2(v.z, v.w, hi.y, lo.y);
}

// ---------------- detect edge dtype (int32 vs int64) ----------------
__global__ void detect_edge_dtype_kernel(const unsigned int* __restrict__ e)
{
    const int t = threadIdx.x;
    unsigned v = 0;
    for (int i = t; i < 512; i += 32) v |= e[2 * i + 1];
    const unsigned any = __ballot_sync(0xffffffffu, v != 0u);
    if (t == 0) g_is64 = (any == 0u) ? 1 : 0;
}

// ---------------- pack edge (int32 or int64) -> uint8 ----------------
__global__ __launch_bounds__(256) void pack_edge_kernel(const void* __restrict__ edge)
{
    const int i = blockIdx.x * blockDim.x + threadIdx.x;
    uchar4 u;
    if (g_is64) {
        const long long* e = (const long long*)edge;
        u.x = (unsigned char)e[(size_t)i*4 + 0];
        u.y = (unsigned char)e[(size_t)i*4 + 1];
        u.z = (unsigned char)e[(size_t)i*4 + 2];
        u.w = (unsigned char)e[(size_t)i*4 + 3];
    } else {
        const int4 v = *(const int4*)((const int*)edge + (size_t)i*4);
        u.x = (unsigned char)v.x; u.y = (unsigned char)v.y;
        u.z = (unsigned char)v.z; u.w = (unsigned char)v.w;
    }
    *(uchar4*)(g_edge8 + (size_t)i*4) = u;
}

// ---------------- fp32 -> bf16 hi/lo splitter ----------------
__global__ __launch_bounds__(256) void split_kernel(
    const float* __restrict__ src, __nv_bfloat16* __restrict__ hi,
    __nv_bfloat16* __restrict__ lo, int n4)
{
    const int i = blockIdx.x * blockDim.x + threadIdx.x;
    if (i >= n4) return;
    uint2 h, l;
    split4(*(const float4*)(src + (size_t)i * 4), h, l);
    *(uint2*)(hi + (size_t)i * 4) = h;
    *(uint2*)(lo + (size_t)i * 4) = l;
}

// ================= HMMA GEMM (pre-split bf16 inputs, cp.async pipelined) =================
// C[M,N] = A[M,K]·B[N,K]^T + bias, 3 products hh+hl+lh, fp32 accum.
// BM=BN=128, BK=32, 256 thr = 8 warps (4m x 2n, warp tile 32x64), double-buffered.
#define GP 40                         /* bf16 pitch (80 B rows) */
#define GTILE (128*GP*2)              /* 10240 B per component */
#define GSTG  (4*GTILE)               /* Ah, Al, Bh, Bl = 40960 B */
#define GEMM_SMEM (2*GSTG)            /* 81920 B */

__global__ __launch_bounds__(256, 2) void gemm_bf16(
    const __nv_bfloat16* __restrict__ Ah, const __nv_bfloat16* __restrict__ Al,
    const __nv_bfloat16* __restrict__ Bh, const __nv_bfloat16* __restrict__ Bl,
    const float* __restrict__ bias,
    float* __restrict__ Cf, __nv_bfloat16* __restrict__ Ch, __nv_bfloat16* __restrict__ Cl,
    int N, int K, int split_out)
{
    extern __shared__ char smc[];
    const uint32_t sb = cvta_smem(smc);
    const int t = threadIdx.x, wid = t >> 5, lane = t & 31;
    const int wm = wid & 3, wn = wid >> 2;
    const int bm = blockIdx.y << 7, bn = blockIdx.x << 7;

    const int r = t >> 1, half = t & 1;
    const __nv_bfloat16* a_h = Ah + (size_t)(bm + r) * K + half * 16;
    const __nv_bfloat16* a_l = Al + (size_t)(bm + r) * K + half * 16;
    const __nv_bfloat16* b_h = Bh + (size_t)(bn + r) * K + half * 16;
    const __nv_bfloat16* b_l = Bl + (size_t)(bn + r) * K + half * 16;
    const uint32_t dstb = (uint32_t)(r * (GP*2) + half * 32);

    const int niter = K >> 5;
    // prologue: stages 0, 1
#pragma unroll
    for (int p = 0; p < 2; p++) {
        const uint32_t d = sb + p * GSTG + dstb;
        const int ko = p * 32;
        CP_ASYNC16(d,             a_h + ko); CP_ASYNC16(d + 16,             a_h + ko + 8);
        CP_ASYNC16(d + GTILE,     a_l + ko); CP_ASYNC16(d + GTILE + 16,     a_l + ko + 8);
        CP_ASYNC16(d + 2*GTILE,   b_h + ko); CP_ASYNC16(d + 2*GTILE + 16,   b_h + ko + 8);
        CP_ASYNC16(d + 3*GTILE,   b_l + ko); CP_ASYNC16(d + 3*GTILE + 16,   b_l + ko + 8);
        CP_COMMIT();
    }

    float acc[2][8][4];
#pragma unroll
    for (int i = 0; i < 2; i++)
#pragma unroll
        for (int j = 0; j < 8; j++)
#pragma unroll
            for (int c = 0; c < 4; c++) acc[i][j][c] = 0.f;

    const uint32_t a_row = (uint32_t)((lane & 7) + ((lane >> 3) & 1) * 8);
    const uint32_t a_kb  = (uint32_t)((lane >> 4) << 4);
    const uint32_t p_row = (uint32_t)((lane & 7) + ((lane >> 4) & 1) * 8);
    const uint32_t p_kb  = (uint32_t)(((lane >> 3) & 1) << 4);

    for (int it = 0; it < niter; it++) {
        if (it == niter - 1) { CP_WAIT0(); } else { CP_WAIT1(); }
        __syncthreads();
        const uint32_t s = sb + (uint32_t)((it & 1) * GSTG);
#pragma unroll
        for (int kk = 0; kk < 2; kk++) {
            uint32_t ah[2][4], al[2][4];
#pragma unroll
            for (int i = 0; i < 2; i++) {
                const uint32_t ad = s + (uint32_t)(wm * 32 + i * 16 + a_row) * (GP*2)
                                  + (uint32_t)(kk * 32) + a_kb;
                ldsm4(ah[i][0], ah[i][1], ah[i][2], ah[i][3], ad);
                ldsm4(al[i][0], al[i][1], al[i][2], al[i][3], ad + GTILE);
            }
#pragma unroll
            for (int jp = 0; jp < 4; jp++) {
                const uint32_t bd = s + 2*GTILE + (uint32_t)(wn * 64 + jp * 16 + p_row) * (GP*2)
                                  + (uint32_t)(kk * 32) + p_kb;
                uint32_t bh0, bh1, bh2, bh3, bl0, bl1, bl2, bl3;
                ldsm4(bh0, bh1, bh2, bh3, bd);
                ldsm4(bl0, bl1, bl2, bl3, bd + GTILE);
#pragma unroll
                for (int i = 0; i < 2; i++) {
                    float* x0 = acc[i][2*jp];
                    float* x1 = acc[i][2*jp+1];
                    mma_bf16(x0[0], x0[1], x0[2], x0[3], ah[i][0], ah[i][1], ah[i][2], ah[i][3], bh0, bh1);
                    mma_bf16(x0[0], x0[1], x0[2], x0[3], ah[i][0], ah[i][1], ah[i][2], ah[i][3], bl0, bl1);
                    mma_bf16(x0[0], x0[1], x0[2], x0[3], al[i][0], al[i][1], al[i][2], al[i][3], bh0, bh1);
                    mma_bf16(x1[0], x1[1], x1[2], x1[3], ah[i][0], ah[i][1], ah[i][2], ah[i][3], bh2, bh3);
                    mma_bf16(x1[0], x1[1], x1[2], x1[3], ah[i][0], ah[i][1], ah[i][2], ah[i][3], bl2, bl3);
                    mma_bf16(x1[0], x1[1], x1[2], x1[3], al[i][0], al[i][1], al[i][2], al[i][3], bh2, bh3);
                }
            }
        }
        __syncthreads();
        if (it + 2 < niter) {
            const uint32_t d = sb + ((it + 2) & 1) * GSTG + dstb;
            const int ko = (it + 2) * 32;
            CP_ASYNC16(d,             a_h + ko); CP_ASYNC16(d + 16,             a_h + ko + 8);
            CP_ASYNC16(d + GTILE,     a_l + ko); CP_ASYNC16(d + GTILE + 16,     a_l + ko + 8);
            CP_ASYNC16(d + 2*GTILE,   b_h + ko); CP_ASYNC16(d + 2*GTILE + 16,   b_h + ko + 8);
            CP_ASYNC16(d + 3*GTILE,   b_l + ko); CP_ASYNC16(d + 3*GTILE + 16,   b_l + ko + 8);
            CP_COMMIT();
        }
    }

    // epilogue
#pragma unroll
    for (int i = 0; i < 2; i++) {
        const int r0 = bm + wm * 32 + i * 16 + (lane >> 2);
#pragma unroll
        for (int j = 0; j < 8; j++) {
            const int c = bn + wn * 64 + j * 8 + (lane & 3) * 2;
            const float2 b2 = *(const float2*)(bias + c);
            const float v00 = acc[i][j][0] + b2.x, v01 = acc[i][j][1] + b2.y;
            const float v10 = acc[i][j][2] + b2.x, v11 = acc[i][j][3] + b2.y;
            if (split_out) {
                uint32_t h0, l0v, h1, l1v;
                split2(v00, v01, h0, l0v);
                split2(v10, v11, h1, l1v);
                *(uint32_t*)(Ch + (size_t)r0 * N + c)       = h0;
                *(uint32_t*)(Cl + (size_t)r0 * N + c)       = l0v;
                *(uint32_t*)(Ch + (size_t)(r0 + 8) * N + c) = h1;
                *(uint32_t*)(Cl + (size_t)(r0 + 8) * N + c) = l1v;
            } else {
                float2 o0 = { v00, v01 }, o1 = { v10, v11 };
                *(float2*)(Cf + (size_t)r0 * N + c)       = o0;
                *(float2*)(Cf + (size_t)(r0 + 8) * N + c) = o1;
            }
        }
    }
}

// ================= HMMA fused flash attention (pre-split bf16 qkv) =================
// grid (8, 64), 256 thr = 8 warps; warp w owns q-rows [16w,16w+16). BKV=64.
// Q fragments in registers (loop-invariant). K/V via cp.async. et via shfl.
#define QP 72                          /* bf16 pitch (144 B rows) */
#define KH_OFF 0
#define KL_OFF (64*QP*2)               /* 9216 */
#define VH_OFF (2*64*QP*2)             /* 18432 */
#define VL_OFF (3*64*QP*2)             /* 27648 */
#define BIAS_OFF (4*64*QP*2)           /* 36864 */
#define BIASP 65
#define ATTN_SMEM (BIAS_OFF + 128*BIASP*4 + 64)   /* ~70.2 KB */

__global__ __launch_bounds__(256, 2) void attn_hmma(
    const float* __restrict__ attn_mask,
    const unsigned char* __restrict__ kpm,
    const float* __restrict__ edge_tab)
{
    extern __shared__ char smc[];
    const uint32_t sb = cvta_smem(smc);
    float* biasS = (float*)(smc + BIAS_OFF);

    const int t = threadIdx.x, w = t >> 5, lane = t & 31;
    const int qb = blockIdx.x, bh = blockIdx.y;
    const int b = bh >> 3, h = bh & 7;
    const int q0 = qb << 7;
    const size_t edge_base = (size_t)b << 20;

    // per-head edge table in registers (race-free, conflict-free)
    const float etreg = edge_tab[(lane & 15) * H_ + h];

    // ldmatrix lane addr components
    const uint32_t a_row = (uint32_t)((lane & 7) + ((lane >> 3) & 1) * 8);
    const uint32_t a_kb  = (uint32_t)((lane >> 4) << 4);
    const uint32_t p_row = (uint32_t)((lane & 7) + ((lane >> 4) & 1) * 8);
    const uint32_t p_kb  = (uint32_t)(((lane >> 3) & 1) << 4);
    const uint32_t v_row = (uint32_t)(lane & 15);
    const uint32_t v_cb  = (uint32_t)((lane >> 4) << 4);

    // ---- prologue: stage Q into K/V region, load fragments to registers ----
    {
        const int r = t >> 1, half = t & 1;
        const __nv_bfloat16* qh = g_qkvh + (size_t)((q0 + r) * B_ + b) * QKV_LD + h * D_ + half * 32;
        const __nv_bfloat16* ql = g_qkvl + (size_t)((q0 + r) * B_ + b) * QKV_LD + h * D_ + half * 32;
        const uint32_t d = sb + (uint32_t)(r * (QP*2) + half * 64);
#pragma unroll
        for (int g = 0; g < 4; g++) {
            CP_ASYNC16(d + g * 16,         qh + g * 8);
            CP_ASYNC16(d + 18432 + g * 16, ql + g * 8);
        }
        CP_COMMIT();
        CP_WAIT0();
    }
    __syncthreads();
    uint32_t qfh[4][4], qfl[4][4];
#pragma unroll
    for (int kk = 0; kk < 4; kk++) {
        const uint32_t qa = sb + (uint32_t)(w * 16 + a_row) * (QP*2) + (uint32_t)(kk * 32) + a_kb;
        ldsm4(qfh[kk][0], qfh[kk][1], qfh[kk][2], qfh[kk][3], qa);
        ldsm4(qfl[kk][0], qfl[kk][1], qfl[kk][2], qfl[kk][3], qa + 18432);
    }
    __syncthreads();   // all warps done reading Q region before K/V overwrite

    float o[8][4];
#pragma unroll
    for (int j = 0; j < 8; j++)
#pragma unroll
        for (int c = 0; c < 4; c++) o[j][c] = 0.f;
    float m0p = -1e30f, m1p = -1e30f, l0 = 0.f, l1 = 0.f;

    for (int kb = 0; kb < 16; kb++) {
        const int m0 = kb << 6;
        if (kb) __syncthreads();

        // ---- cp.async K/V tiles [64 x 64] hi/lo ----
        {
            const int r = t >> 2, q4 = t & 3;
            const size_t rowb = (size_t)((m0 + r) * B_ + b) * QKV_LD + h * D_;
            const __nv_bfloat16* kh = g_qkvh + rowb + E_  + q4 * 16;
            const __nv_bfloat16* kl = g_qkvl + rowb + E_  + q4 * 16;
            const __nv_bfloat16* vh = g_qkvh + rowb + 2*E_ + q4 * 16;
            const __nv_bfloat16* vl = g_qkvl + rowb + 2*E_ + q4 * 16;
            const uint32_t d = sb + (uint32_t)(r * (QP*2) + q4 * 32);
            CP_ASYNC16(d + KH_OFF,      kh); CP_ASYNC16(d + KH_OFF + 16,  kh + 8);
            CP_ASYNC16(d + KL_OFF,      kl); CP_ASYNC16(d + KL_OFF + 16,  kl + 8);
            CP_ASYNC16(d + VH_OFF,      vh); CP_ASYNC16(d + VH_OFF + 16,  vh + 8);
            CP_ASYNC16(d + VL_OFF,      vl); CP_ASYNC16(d + VL_OFF + 16,  vl + 8);
            CP_COMMIT();
        }
        // ---- bias tile [128 x 64] = mask + edge (shfl) + key padding ----
        {
            const int i = t >> 1, c0 = (t & 1) << 5;
            const int qi = q0 + i;
            const float* mp = attn_mask + (size_t)qi * L_ + m0 + c0;
            union { uint4 u[2]; unsigned char c[32]; } eu, ku;
            eu.u[0] = *(const uint4*)(g_edge8 + edge_base + (size_t)qi * L_ + m0 + c0);
            eu.u[1] = *(const uint4*)(g_edge8 + edge_base + (size_t)qi * L_ + m0 + c0 + 16);
            ku.u[0] = *(const uint4*)(kpm + b * L_ + m0 + c0);
            ku.u[1] = *(const uint4*)(kpm + b * L_ + m0 + c0 + 16);
            float* bo = biasS + i * BIASP + c0;
#pragma unroll
            for (int q = 0; q < 8; q++) {
                const float4 mv = *(const float4*)(mp + q * 4);
#pragma unroll
                for (int e = 0; e < 4; e++) {
                    const int idx = q * 4 + e;
                    const float mval = (e == 0) ? mv.x : (e == 1) ? mv.y : (e == 2) ? mv.z : mv.w;
                    const float ev = __shfl_sync(0xffffffffu, etreg, eu.c[idx]);
                    bo[idx] = mval + ev + (ku.c[idx] ? -1e30f : 0.f);
                }
            }
        }
        CP_WAIT0();
        __syncthreads();

        // ---- S = Q K^T (16 x 64 per warp), 3 products, Q from regs ----
        float sacc[8][4];
#pragma unroll
        for (int j = 0; j < 8; j++)
#pragma unroll
            for (int c = 0; c < 4; c++) sacc[j][c] = 0.f;
#pragma unroll
        for (int kk = 0; kk < 4; kk++) {
#pragma unroll
            for (int jp = 0; jp < 4; jp++) {
                const uint32_t ka = sb + KH_OFF + (uint32_t)(jp * 16 + p_row) * (QP*2)
                                  + (uint32_t)(kk * 32) + p_kb;
                uint32_t kh0, kh1, kh2, kh3, kl0, kl1, kl2, kl3;
                ldsm4(kh0, kh1, kh2, kh3, ka);
                ldsm4(kl0, kl1, kl2, kl3, ka + KL_OFF);
                float* s0 = sacc[2*jp];
                float* s1 = sacc[2*jp+1];
                mma_bf16(s0[0], s0[1], s0[2], s0[3], qfh[kk][0], qfh[kk][1], qfh[kk][2], qfh[kk][3], kh0, kh1);
                mma_bf16(s0[0], s0[1], s0[2], s0[3], qfh[kk][0], qfh[kk][1], qfh[kk][2], qfh[kk][3], kl0, kl1);
                mma_bf16(s0[0], s0[1], s0[2], s0[3], qfl[kk][0], qfl[kk][1], qfl[kk][2], qfl[kk][3], kh0, kh1);
                mma_bf16(s1[0], s1[1], s1[2], s1[3], qfh[kk][0], qfh[kk][1], qfh[kk][2], qfh[kk][3], kh2, kh3);
                mma_bf16(s1[0], s1[1], s1[2], s1[3], qfh[kk][0], qfh[kk][1], qfh[kk][2], qfh[kk][3], kl2, kl3);
                mma_bf16(s1[0], s1[1], s1[2], s1[3], qfl[kk][0], qfl[kk][1], qfl[kk][2], qfl[kk][3], kh2, kh3);
            }
        }
        // ---- scale + bias ----
        {
            const int rl = w * 16 + (lane >> 2);
            const float* bi0 = biasS + rl * BIASP;
            const float* bi1 = biasS + (rl + 8) * BIASP;
#pragma unroll
            for (int j = 0; j < 8; j++) {
                const int c = j * 8 + (lane & 3) * 2;
                sacc[j][0] = sacc[j][0] * 0.125f + bi0[c];
                sacc[j][1] = sacc[j][1] * 0.125f + bi0[c + 1];
                sacc[j][2] = sacc[j][2] * 0.125f + bi1[c];
                sacc[j][3] = sacc[j][3] * 0.125f + bi1[c + 1];
            }
        }
        // ---- online softmax ----
        float mx0 = -1e30f, mx1 = -1e30f;
#pragma unroll
        for (int j = 0; j < 8; j++) {
            mx0 = fmaxf(mx0, fmaxf(sacc[j][0], sacc[j][1]));
            mx1 = fmaxf(mx1, fmaxf(sacc[j][2], sacc[j][3]));
        }
        mx0 = fmaxf(mx0, __shfl_xor_sync(0xffffffffu, mx0, 1));
        mx0 = fmaxf(mx0, __shfl_xor_sync(0xffffffffu, mx0, 2));
        mx1 = fmaxf(mx1, __shfl_xor_sync(0xffffffffu, mx1, 1));
        mx1 = fmaxf(mx1, __shfl_xor_sync(0xffffffffu, mx1, 2));
        const float mn0 = fmaxf(m0p, mx0), mn1 = fmaxf(m1p, mx1);
        const float c0 = __expf(m0p - mn0), c1 = __expf(m1p - mn1);
        m0p = mn0; m1p = mn1;
        float s0 = 0.f, s1 = 0.f;
#pragma unroll
        for (int j = 0; j < 8; j++) {
            sacc[j][0] = __expf(sacc[j][0] - mn0); s0 += sacc[j][0];
            sacc[j][1] = __expf(sacc[j][1] - mn0); s0 += sacc[j][1];
            sacc[j][2] = __expf(sacc[j][2] - mn1); s1 += sacc[j][2];
            sacc[j][3] = __expf(sacc[j][3] - mn1); s1 += sacc[j][3];
        }
        s0 += __shfl_xor_sync(0xffffffffu, s0, 1);
        s0 += __shfl_xor_sync(0xffffffffu, s0, 2);
        s1 += __shfl_xor_sync(0xffffffffu, s1, 1);
        s1 += __shfl_xor_sync(0xffffffffu, s1, 2);
        l0 = l0 * c0 + s0;
        l1 = l1 * c1 + s1;
#pragma unroll
        for (int j = 0; j < 8; j++) {
            o[j][0] *= c0; o[j][1] *= c0; o[j][2] *= c1; o[j][3] *= c1;
        }

        // ---- O += P V ----
#pragma unroll
        for (int kk = 0; kk < 4; kk++) {
            uint32_t ph[4], pl[4];
#pragma unroll
            for (int half = 0; half < 2; half++) {
                const int jt = 2 * kk + half;
                split2(sacc[jt][0], sacc[jt][1], ph[2*half + 0], pl[2*half + 0]);
                split2(sacc[jt][2], sacc[jt][3], ph[2*half + 1], pl[2*half + 1]);
            }
#pragma unroll
            for (int jp = 0; jp < 4; jp++) {
                const uint32_t va = sb + VH_OFF + (uint32_t)(kk * 16 + v_row) * (QP*2)
                                  + (uint32_t)(jp * 32) + v_cb;
                uint32_t vh0, vh1, vh2, vh3, vl0, vl1, vl2, vl3;
                ldsm4t(vh0, vh1, vh2, vh3, va);
                ldsm4t(vl0, vl1, vl2, vl3, va + (VL_OFF - VH_OFF));
                float* o0 = o[2*jp];
                float* o1 = o[2*jp+1];
                mma_bf16(o0[0], o0[1], o0[2], o0[3], ph[0], ph[1], ph[2], ph[3], vh0, vh1);
                mma_bf16(o0[0], o0[1], o0[2], o0[3], ph[0], ph[1], ph[2], ph[3], vl0, vl1);
                mma_bf16(o0[0], o0[1], o0[2], o0[3], pl[0], pl[1], pl[2], pl[3], vh0, vh1);
                mma_bf16(o1[0], o1[1], o1[2], o1[3], ph[0], ph[1], ph[2], ph[3], vh2, vh3);
                mma_bf16(o1[0], o1[1], o1[2], o1[3], ph[0], ph[1], ph[2], ph[3], vl2, vl3);
                mma_bf16(o1[0], o1[1], o1[2], o1[3], pl[0], pl[1], pl[2], pl[3], vh2, vh3);
            }
        }
    }

    // ---- normalize and write split bf16 hi/lo [row=l*B+b][E] ----
    {
        const float inv0 = 1.f / l0, inv1 = 1.f / l1;
        const int gr0 = q0 + w * 16 + (lane >> 2);
        const size_t row0 = (size_t)(gr0 * B_ + b) * E_;
        const size_t row1 = (size_t)((gr0 + 8) * B_ + b) * E_;
#pragma unroll
        for (int j = 0; j < 8; j++) {
            const int c = h * D_ + j * 8 + (lane & 3) * 2;
            uint32_t h0, l0v, h1, l1v;
            split2(o[j][0] * inv0, o[j][1] * inv0, h0, l0v);
            split2(o[j][2] * inv1, o[j][3] * inv1, h1, l1v);
            *(uint32_t*)(g_atth + row0 + c) = h0;
            *(uint32_t*)(g_attl + row0 + c) = l0v;
            *(uint32_t*)(g_atth + row1 + c) = h1;
            *(uint32_t*)(g_attl + row1 + c) = l1v;
        }
    }
}

// ---------------- launch ----------------
extern "C" void kernel_launch(void* const* d_in, const int* in_sizes, int n_in,
                              void* d_out, int out_size)
{
    const float*         x         = (const float*)d_in[0];
    const void*          edge      = d_in[1];
    const float*         attn_mask = (const float*)d_in[2];
    const unsigned char* kpm       = (const unsigned char*)d_in[3];
    const float*         in_w      = (const float*)d_in[4];
    const float*         in_b      = (const float*)d_in[5];
    const float*         out_w     = (const float*)d_in[6];
    const float*         out_b     = (const float*)d_in[7];
    const float*         edge_tab  = (const float*)d_in[8];
    float* out = (float*)d_out;

    __nv_bfloat16 *xh, *xl, *iwh, *iwl, *owh, *owl, *qkvh, *qkvl, *atth, *attl;
    cudaGetSymbolAddress((void**)&xh,   g_xh);
    cudaGetSymbolAddress((void**)&xl,   g_xl);
    cudaGetSymbolAddress((void**)&iwh,  g_iwh);
    cudaGetSymbolAddress((void**)&iwl,  g_iwl);
    cudaGetSymbolAddress((void**)&owh,  g_owh);
    cudaGetSymbolAddress((void**)&owl,  g_owl);
    cudaGetSymbolAddress((void**)&qkvh, g_qkvh);
    cudaGetSymbolAddress((void**)&qkvl, g_qkvl);
    cudaGetSymbolAddress((void**)&atth, g_atth);
    cudaGetSymbolAddress((void**)&attl, g_attl);

    cudaFuncSetAttribute(gemm_bf16, cudaFuncAttributeMaxDynamicSharedMemorySize, GEMM_SMEM);
    cudaFuncSetAttribute(attn_hmma, cudaFuncAttributeMaxDynamicSharedMemorySize, ATTN_SMEM);

    detect_edge_dtype_kernel<<<1, 32>>>((const unsigned int*)edge);
    pack_edge_kernel<<<(B_ * L_ * L_) / (256 * 4), 256>>>(edge);

    // pre-split inputs to bf16 hi/lo
    split_kernel<<<(ROWS_ * E_ / 4 + 255) / 256, 256>>>(x, xh, xl, ROWS_ * E_ / 4);
    split_kernel<<<(QKV_LD * E_ / 4 + 255) / 256, 256>>>(in_w, iwh, iwl, QKV_LD * E_ / 4);
    split_kernel<<<(E_ * E_ / 4 + 255) / 256, 256>>>(out_w, owh, owl, E_ * E_ / 4);

    // QKV projection -> split bf16 qkv
    gemm_bf16<<<dim3(QKV_LD / 128, ROWS_ / 128), 256, GEMM_SMEM>>>(
        xh, xl, iwh, iwl, in_b, nullptr, qkvh, qkvl, QKV_LD, E_, 1);

    // fused attention -> split bf16 att
    attn_hmma<<<dim3(L_ / 128, B_ * H_), 256, ATTN_SMEM>>>(attn_mask, kpm, edge_tab);

    // output projection -> fp32 out
    gemm_bf16<<<dim3(E_ / 128, ROWS_ / 128), 256, GEMM_SMEM>>>(
        atth, attl, owh, owl, out_b, out, nullptr, nullptr, E_, E_, 0);
}